// round 15
// baseline (speedup 1.0000x reference)
#include <cuda_runtime.h>

#define SK_N      512
#define SK_ITERS  21
#define SK_THR    512          // 16 warps, reg cap 128: room for 2 row chains (ILP-2)
#define SK_NCLUST 64           // 64 clusters x 2 CTAs = 128 CTAs; 64MB hot set << L2
#define SK_ROWS_PER_CTA 256
#define SK_RPW    16           // rows per warp (16 warps x 16 = 256), processed in pairs
#define SK_K2     144.26950408889634f   // 100 * log2(e): work in log2 domain
#define SK_CONV   1.52587890625e-05f    // 2^-16 per-iter v-change threshold
#define SK_B      112.0f                // exponent bias: term reach z-u > -238
#define SK_2B     5.192296858534828e33f // 2^112
#define SK_FLOOR  1.2446e-35f           // 2^-116 colp init (=> fallback dv ~ -222)

typedef unsigned long long sk_u64;

__device__ __forceinline__ float ex2f_(float x) {
    float r; asm("ex2.approx.ftz.f32 %0, %1;" : "=f"(r) : "f"(x)); return r;
}
__device__ __forceinline__ float lg2f_(float x) {
    float r; asm("lg2.approx.ftz.f32 %0, %1;" : "=f"(r) : "f"(x)); return r;
}
__device__ __forceinline__ float rcpf_(float x) {
    float r; asm("rcp.approx.ftz.f32 %0, %1;" : "=f"(r) : "f"(x)); return r;
}
// monotonic float<->uint order transform (EXACT warp max via __reduce_max_sync)
__device__ __forceinline__ unsigned f2ord(float f) {
    unsigned b = __float_as_uint(f);
    return b ^ (unsigned)(((int)b >> 31) | 0x80000000);
}
__device__ __forceinline__ float ord2f(unsigned k) {
    return __uint_as_float(k ^ (unsigned)((~(int)k >> 31) | 0x80000000));
}
// ---- packed f32x2 (Blackwell; ptxas never auto-fuses these) ----
__device__ __forceinline__ sk_u64 pk2_(float lo, float hi) {
    sk_u64 r; asm("mov.b64 %0, {%1, %2};" : "=l"(r) : "f"(lo), "f"(hi)); return r;
}
__device__ __forceinline__ void up2_(sk_u64 p, float& lo, float& hi) {
    asm("mov.b64 {%0, %1}, %2;" : "=f"(lo), "=f"(hi) : "l"(p));
}
__device__ __forceinline__ sk_u64 fma2_(sk_u64 a, sk_u64 b, sk_u64 c) {
    sk_u64 r; asm("fma.rn.f32x2 %0, %1, %2, %3;" : "=l"(r) : "l"(a), "l"(b), "l"(c)); return r;
}
__device__ __forceinline__ sk_u64 add2_(sk_u64 a, sk_u64 b) {
    sk_u64 r; asm("add.rn.f32x2 %0, %1, %2;" : "=l"(r) : "l"(a), "l"(b)); return r;
}
__device__ __forceinline__ unsigned cluster_rank_() {
    unsigned r; asm("mov.u32 %0, %%cluster_ctarank;" : "=r"(r)); return r;
}
__device__ __forceinline__ void st_peer_f32(unsigned addr, unsigned peer, float v) {
    asm volatile(
        "{ .reg .b32 r; mapa.shared::cluster.u32 r, %0, %1;"
        "  st.shared::cluster.f32 [r], %2; }"
        :: "r"(addr), "r"(peer), "f"(v) : "memory");
}
__device__ __forceinline__ void cluster_sync_() {
    asm volatile("barrier.cluster.arrive.aligned;" ::: "memory");
    asm volatile("barrier.cluster.wait.aligned;"   ::: "memory");
}

// SMEM floats: nv[512] (= -v) | M_s[512] | S_s[512] | stg_p[16*512] | pex[2*512]
#define OFF_V    0
#define OFF_M    512
#define OFF_S    1024
#define OFF_SP   1536
#define OFF_PEX  (1536 + 16*512)
#define SK_SMEM_FLOATS (1536 + 16*512 + 1024)
#define SK_SMEM_BYTES  (SK_SMEM_FLOATS * 4)

// Cluster of 2 CTAs per matrix; 64 concurrent matrices L2-resident.
// ILP-2: each warp runs TWO independent row chains at once (separate z regs,
// max, redux, exp, shfl-sum, rcp) so chain latency is hidden by the sibling
// chain instead of extra warps. Math identical to R14 (exponent-bias scheme):
//   Mb = M-112; t = exp2(z-Mb) (<=2^112); S2 = sum t
//   colp += t * (rcp(S2)*2^112);  u = Mb + log2(S2) (deferred to output)
//   nv_j -= (log2(P_local+P_peer) - 112)
__global__ void __launch_bounds__(SK_THR, 1) __cluster_dims__(2, 1, 1)
sinkhorn_fused(const float* __restrict__ x, float* __restrict__ out, int nmat)
{
    extern __shared__ float smem[];
    float* v_s   = smem + OFF_V;     // holds -v
    float* M_s   = smem + OFF_M;
    float* S_s   = smem + OFF_S;
    float* stg_p = smem + OFF_SP;
    float* pex   = smem + OFF_PEX;
    const unsigned smem_b = (unsigned)__cvta_generic_to_shared(smem);

    const int tid  = threadIdx.x;
    const int lane = tid & 31;
    const int wid  = tid >> 5;                 // 0..15
    const unsigned FULL = 0xffffffffu;
    const unsigned rank = cluster_rank_();
    const unsigned peer = rank ^ 1u;
    const int row0 = (int)rank * SK_ROWS_PER_CTA;
    const sk_u64 K2_2 = pk2_(SK_K2, SK_K2);

    const int cid    = blockIdx.x >> 1;
    const int nclust = gridDim.x >> 1;

    for (int m = cid; m < nmat; m += nclust) {
        const float* __restrict__ X = x   + (size_t)m * SK_N * SK_N;
        float*       __restrict__ O = out + (size_t)m * SK_N * SK_N;

        v_s[tid] = 0.0f;
        __syncthreads();

        for (int it = 0; it < SK_ITERS; ++it) {
            const int par = it & 1;

            // hoist nv into packed registers ONCE per iteration
            sk_u64 colv2[8];
            {
                const float4* vr = reinterpret_cast<const float4*>(v_s);
                #pragma unroll
                for (int k = 0; k < 4; ++k) {
                    float4 nv = vr[lane + 32 * k];
                    colv2[2*k]   = pk2_(nv.x, nv.y);
                    colv2[2*k+1] = pk2_(nv.z, nv.w);
                }
            }
            // floor init: dead columns still yield P > 0 (self-corrects;
            // v_new is analytically independent of v_old)
            sk_u64 colp2[8];
            const sk_u64 FLOOR2 = pk2_(SK_FLOOR, SK_FLOOR);
            #pragma unroll
            for (int e = 0; e < 8; ++e) colp2[e] = FLOOR2;

            const int rbase = row0 + wid * SK_RPW;

            // two independent row chains per trip (ILP-2)
            #pragma unroll 1
            for (int rr = 0; rr < SK_RPW; rr += 2) {
                const int rA = rbase + rr;
                const int rB = rA + 1;
                const float4* xrA = reinterpret_cast<const float4*>(X + (size_t)rA * SK_N);
                const float4* xrB = reinterpret_cast<const float4*>(X + (size_t)rB * SK_N);

                // both rows' loads issued up front (MLP 8)
                sk_u64 zA[8], zB[8];
                #pragma unroll
                for (int k = 0; k < 4; ++k) {
                    float4 xa = __ldg(xrA + lane + 32 * k);
                    float4 xb = __ldg(xrB + lane + 32 * k);
                    zA[2*k]   = fma2_(pk2_(xa.x, xa.y), K2_2, colv2[2*k]);
                    zA[2*k+1] = fma2_(pk2_(xa.z, xa.w), K2_2, colv2[2*k+1]);
                    zB[2*k]   = fma2_(pk2_(xb.x, xb.y), K2_2, colv2[2*k]);
                    zB[2*k+1] = fma2_(pk2_(xb.z, xb.w), K2_2, colv2[2*k+1]);
                }

                // exact row maxes (two independent chains)
                float mA = -3.0e38f, mB = -3.0e38f;
                #pragma unroll
                for (int e = 0; e < 8; ++e) {
                    float a, b; up2_(zA[e], a, b);
                    mA = fmaxf(mA, fmaxf(a, b));
                    float c, d; up2_(zB[e], c, d);
                    mB = fmaxf(mB, fmaxf(c, d));
                }
                const float MA = ord2f(__reduce_max_sync(FULL, f2ord(mA)));
                const float MB = ord2f(__reduce_max_sync(FULL, f2ord(mB)));

                // biased exp + packed sums
                const sk_u64 mMbA = pk2_(SK_B - MA, SK_B - MA);
                const sk_u64 mMbB = pk2_(SK_B - MB, SK_B - MB);
                sk_u64 sA = pk2_(0.0f, 0.0f), sB = pk2_(0.0f, 0.0f);
                #pragma unroll
                for (int e = 0; e < 8; ++e) {
                    sk_u64 wA = add2_(zA[e], mMbA);
                    sk_u64 wB = add2_(zB[e], mMbB);
                    float a, b; up2_(wA, a, b);
                    float c, d; up2_(wB, c, d);
                    sk_u64 tA = pk2_(ex2f_(a), ex2f_(b));
                    sk_u64 tB = pk2_(ex2f_(c), ex2f_(d));
                    zA[e] = tA; zB[e] = tB;
                    sA = add2_(sA, tA);
                    sB = add2_(sB, tB);
                }
                float al, ah, bl, bh;
                up2_(sA, al, ah); up2_(sB, bl, bh);
                float S2A = al + ah, S2B = bl + bh;
                #pragma unroll
                for (int o = 16; o > 0; o >>= 1) {
                    S2A += __shfl_xor_sync(FULL, S2A, o);
                    S2B += __shfl_xor_sync(FULL, S2B, o);
                }

                // S2 in [2^112, 2^121]; rcp stays normal
                const float invA = rcpf_(S2A) * SK_2B;
                const float invB = rcpf_(S2B) * SK_2B;
                if (lane == 0) {
                    M_s[rA] = MA - SK_B; S_s[rA] = S2A;
                    M_s[rB] = MB - SK_B; S_s[rB] = S2B;
                }

                // colp += exp2(z - u + 112)  (packed fma, both rows)
                const sk_u64 iA2 = pk2_(invA, invA);
                const sk_u64 iB2 = pk2_(invB, invB);
                #pragma unroll
                for (int e = 0; e < 8; ++e) {
                    colp2[e] = fma2_(zA[e], iA2, colp2[e]);
                    colp2[e] = fma2_(zB[e], iB2, colp2[e]);
                }
            }

            // stage per-warp column partials (conflict-free float4)
            {
                float4* sp = reinterpret_cast<float4*>(stg_p + wid * 512);
                #pragma unroll
                for (int k = 0; k < 4; ++k) {
                    float4 o4;
                    up2_(colp2[2*k],   o4.x, o4.y);
                    up2_(colp2[2*k+1], o4.z, o4.w);
                    sp[lane + 32 * k] = o4;
                }
            }
            __syncthreads();

            // combine: thread j owns column j over 16 warp partials
            float Pl = 0.0f;
            #pragma unroll
            for (int w = 0; w < 16; ++w) Pl += stg_p[w * 512 + tid];
            st_peer_f32(smem_b + (OFF_PEX + par * 512 + tid) * 4, peer, Pl);

            cluster_sync_();   // release our DSMEM store / acquire peer's

            const float P  = Pl + pex[par * 512 + tid];   // > 0 by floor
            const float dv = lg2f_(P) - SK_B;
            v_s[tid] -= dv;          // nv convention: nv -= dv
            const int active = __syncthreads_count(fabsf(dv) > SK_CONV);
            if (active == 0) break;   // identical in both CTAs -> coherent exit
        }

        // output: exp2(s + nv - u), u = Mb + log2(S2); packed, streaming
        {
            sk_u64 colv2[8];
            const float4* vr = reinterpret_cast<const float4*>(v_s);
            #pragma unroll
            for (int k = 0; k < 4; ++k) {
                float4 nv = vr[lane + 32 * k];
                colv2[2*k]   = pk2_(nv.x, nv.y);
                colv2[2*k+1] = pk2_(nv.z, nv.w);
            }
            #pragma unroll 1
            for (int rr = 0; rr < SK_RPW; ++rr) {
                const int r = row0 + wid * SK_RPW + rr;
                const float ur = M_s[r] + lg2f_(S_s[r]);   // true u (bias cancels)
                const sk_u64 mu2 = pk2_(-ur, -ur);
                const float4* xr = reinterpret_cast<const float4*>(X + (size_t)r * SK_N);
                float4* orow = reinterpret_cast<float4*>(O + (size_t)r * SK_N);
                #pragma unroll
                for (int k = 0; k < 4; ++k) {
                    float4 xv = __ldcs(xr + lane + 32 * k);
                    sk_u64 a2 = add2_(fma2_(pk2_(xv.x, xv.y), K2_2, colv2[2*k]),   mu2);
                    sk_u64 b2 = add2_(fma2_(pk2_(xv.z, xv.w), K2_2, colv2[2*k+1]), mu2);
                    float4 o;
                    { float a, b; up2_(a2, a, b); o.x = ex2f_(a); o.y = ex2f_(b); }
                    { float a, b; up2_(b2, a, b); o.z = ex2f_(a); o.w = ex2f_(b); }
                    __stcs(orow + lane + 32 * k, o);
                }
            }
        }
        // protect exchange buffers + v_s before the next matrix starts
        cluster_sync_();
        __syncthreads();
    }
}

extern "C" void kernel_launch(void* const* d_in, const int* in_sizes, int n_in,
                              void* d_out, int out_size)
{
    const float* x = (const float*)d_in[0];
    float* out = (float*)d_out;
    const int nmat = in_sizes[0] / (SK_N * SK_N);

    cudaFuncSetAttribute(sinkhorn_fused,
                         cudaFuncAttributeMaxDynamicSharedMemorySize, SK_SMEM_BYTES);

    int nclust = nmat < SK_NCLUST ? nmat : SK_NCLUST;
    sinkhorn_fused<<<2 * nclust, SK_THR, SK_SMEM_BYTES>>>(x, out, nmat);
}

// round 16
// speedup vs baseline: 1.1658x; 1.1658x over previous
#include <cuda_runtime.h>

#define SK_N      512
#define SK_ITERS  21
#define SK_THR    640          // 20 warps, reg cap 102: R14 chain + 16 prefetch regs
#define SK_NCLUST 64           // 64 clusters x 2 CTAs = 128 CTAs; 64MB hot set << L2
#define SK_ROWS_PER_CTA 256
#define SK_K2     144.26950408889634f   // 100 * log2(e): work in log2 domain
#define SK_CONV   1.52587890625e-05f    // 2^-16 per-iter v-change threshold
#define SK_B      112.0f                // exponent bias: term reach z-u > -238
#define SK_2B     5.192296858534828e33f // 2^112
#define SK_FLOOR  1.2446e-35f           // 2^-116 colp init (=> fallback dv ~ -222)

typedef unsigned long long sk_u64;

__device__ __forceinline__ float ex2f_(float x) {
    float r; asm("ex2.approx.ftz.f32 %0, %1;" : "=f"(r) : "f"(x)); return r;
}
__device__ __forceinline__ float lg2f_(float x) {
    float r; asm("lg2.approx.ftz.f32 %0, %1;" : "=f"(r) : "f"(x)); return r;
}
__device__ __forceinline__ float rcpf_(float x) {
    float r; asm("rcp.approx.ftz.f32 %0, %1;" : "=f"(r) : "f"(x)); return r;
}
// monotonic float<->uint order transform (EXACT warp max via __reduce_max_sync)
__device__ __forceinline__ unsigned f2ord(float f) {
    unsigned b = __float_as_uint(f);
    return b ^ (unsigned)(((int)b >> 31) | 0x80000000);
}
__device__ __forceinline__ float ord2f(unsigned k) {
    return __uint_as_float(k ^ (unsigned)((~(int)k >> 31) | 0x80000000));
}
// ---- packed f32x2 (Blackwell; ptxas never auto-fuses these) ----
__device__ __forceinline__ sk_u64 pk2_(float lo, float hi) {
    sk_u64 r; asm("mov.b64 %0, {%1, %2};" : "=l"(r) : "f"(lo), "f"(hi)); return r;
}
__device__ __forceinline__ void up2_(sk_u64 p, float& lo, float& hi) {
    asm("mov.b64 {%0, %1}, %2;" : "=f"(lo), "=f"(hi) : "l"(p));
}
__device__ __forceinline__ sk_u64 fma2_(sk_u64 a, sk_u64 b, sk_u64 c) {
    sk_u64 r; asm("fma.rn.f32x2 %0, %1, %2, %3;" : "=l"(r) : "l"(a), "l"(b), "l"(c)); return r;
}
__device__ __forceinline__ sk_u64 add2_(sk_u64 a, sk_u64 b) {
    sk_u64 r; asm("add.rn.f32x2 %0, %1, %2;" : "=l"(r) : "l"(a), "l"(b)); return r;
}
__device__ __forceinline__ unsigned cluster_rank_() {
    unsigned r; asm("mov.u32 %0, %%cluster_ctarank;" : "=r"(r)); return r;
}
__device__ __forceinline__ void st_peer_f32(unsigned addr, unsigned peer, float v) {
    asm volatile(
        "{ .reg .b32 r; mapa.shared::cluster.u32 r, %0, %1;"
        "  st.shared::cluster.f32 [r], %2; }"
        :: "r"(addr), "r"(peer), "f"(v) : "memory");
}
__device__ __forceinline__ void cluster_sync_() {
    asm volatile("barrier.cluster.arrive.aligned;" ::: "memory");
    asm volatile("barrier.cluster.wait.aligned;"   ::: "memory");
}

// SMEM floats: nv[512] (= -v) | M_s[512] | S_s[512] | stg_p[20*512] | pex[2*512]
#define OFF_V    0
#define OFF_M    512
#define OFF_S    1024
#define OFF_SP   1536
#define OFF_PEX  (1536 + 20*512)
#define SK_SMEM_FLOATS (1536 + 20*512 + 1024)
#define SK_SMEM_BYTES  (SK_SMEM_FLOATS * 4)

// Cluster of 2 CTAs per matrix; 64 concurrent matrices L2-resident.
// R14 structure (nv in regs, exact redux max, packed f32x2, exponent bias)
// + depth-1 row prefetch: next row's 4 LDG.128 issue BEFORE the current
// row's reduction chain, hiding the L2 hit latency at each chain head.
//   Mb = M-112; t = exp2(z-Mb) (<=2^112); S2 = sum t
//   colp += t * (rcp(S2)*2^112);  u = Mb + log2(S2) (deferred to output)
//   nv_j -= (log2(P_local+P_peer) - 112)
__global__ void __launch_bounds__(SK_THR, 1) __cluster_dims__(2, 1, 1)
sinkhorn_fused(const float* __restrict__ x, float* __restrict__ out, int nmat)
{
    extern __shared__ float smem[];
    float* v_s   = smem + OFF_V;     // holds -v
    float* M_s   = smem + OFF_M;
    float* S_s   = smem + OFF_S;
    float* stg_p = smem + OFF_SP;
    float* pex   = smem + OFF_PEX;
    const unsigned smem_b = (unsigned)__cvta_generic_to_shared(smem);

    const int tid  = threadIdx.x;
    const int lane = tid & 31;
    const int wid  = tid >> 5;                 // 0..19
    const unsigned FULL = 0xffffffffu;
    const unsigned rank = cluster_rank_();
    const unsigned peer = rank ^ 1u;
    const int row0 = (int)rank * SK_ROWS_PER_CTA;
    const sk_u64 K2_2 = pk2_(SK_K2, SK_K2);

    // 256 rows over 20 warps: warps 0-15 take 13 rows, warps 16-19 take 12
    const int nrows = (wid < 16) ? 13 : 12;
    const int rwoff = (wid < 16) ? wid * 13 : 208 + (wid - 16) * 12;

    const int cid    = blockIdx.x >> 1;
    const int nclust = gridDim.x >> 1;

    for (int m = cid; m < nmat; m += nclust) {
        const float* __restrict__ X = x   + (size_t)m * SK_N * SK_N;
        float*       __restrict__ O = out + (size_t)m * SK_N * SK_N;

        if (tid < SK_N) v_s[tid] = 0.0f;
        __syncthreads();

        for (int it = 0; it < SK_ITERS; ++it) {
            const int par = it & 1;

            // hoist nv into packed registers ONCE per iteration
            sk_u64 colv2[8];
            {
                const float4* vr = reinterpret_cast<const float4*>(v_s);
                #pragma unroll
                for (int k = 0; k < 4; ++k) {
                    float4 nv = vr[lane + 32 * k];
                    colv2[2*k]   = pk2_(nv.x, nv.y);
                    colv2[2*k+1] = pk2_(nv.z, nv.w);
                }
            }
            // floor init: dead columns still yield P > 0 (self-corrects;
            // v_new is analytically independent of v_old)
            sk_u64 colp2[8];
            const sk_u64 FLOOR2 = pk2_(SK_FLOOR, SK_FLOOR);
            #pragma unroll
            for (int e = 0; e < 8; ++e) colp2[e] = FLOOR2;

            const int rbase = row0 + rwoff;

            // depth-1 prefetch: row rbase loaded before the loop
            float4 pf[4];
            {
                const float4* x0 = reinterpret_cast<const float4*>(X + (size_t)rbase * SK_N);
                #pragma unroll
                for (int k = 0; k < 4; ++k) pf[k] = __ldg(x0 + lane + 32 * k);
            }

            #pragma unroll 1
            for (int rr = 0; rr < nrows; ++rr) {
                const int r = rbase + rr;

                // consume prefetch into z = s + nv (packed fma)
                sk_u64 z2[8];
                #pragma unroll
                for (int k = 0; k < 4; ++k) {
                    z2[2*k]   = fma2_(pk2_(pf[k].x, pf[k].y), K2_2, colv2[2*k]);
                    z2[2*k+1] = fma2_(pk2_(pf[k].z, pf[k].w), K2_2, colv2[2*k+1]);
                }
                // issue next row's loads NOW — they fly during the reduction
                if (rr + 1 < nrows) {
                    const float4* xn = reinterpret_cast<const float4*>(X + (size_t)(r + 1) * SK_N);
                    #pragma unroll
                    for (int k = 0; k < 4; ++k) pf[k] = __ldg(xn + lane + 32 * k);
                }

                // exact row max: local fmnmx chain + single REDUX
                float ml = -3.0e38f;
                #pragma unroll
                for (int e = 0; e < 8; ++e) {
                    float a, b; up2_(z2[e], a, b);
                    ml = fmaxf(ml, fmaxf(a, b));
                }
                const float M = ord2f(__reduce_max_sync(FULL, f2ord(ml)));

                // biased exp + packed sum: t = exp2(z - (M-112)) <= 2^112
                const sk_u64 mMb2 = pk2_(SK_B - M, SK_B - M);
                sk_u64 s2acc = pk2_(0.0f, 0.0f);
                #pragma unroll
                for (int e = 0; e < 8; ++e) {
                    sk_u64 w = add2_(z2[e], mMb2);
                    float a, b; up2_(w, a, b);
                    sk_u64 t = pk2_(ex2f_(a), ex2f_(b));
                    z2[e] = t;
                    s2acc = add2_(s2acc, t);
                }
                float sl, sh; up2_(s2acc, sl, sh);
                float S2 = sl + sh;
                #pragma unroll
                for (int o = 16; o > 0; o >>= 1)
                    S2 += __shfl_xor_sync(FULL, S2, o);

                // S2 in [2^112, 2^121]; rcp stays normal
                const float invSb = rcpf_(S2) * SK_2B;
                if (lane == 0) { M_s[r] = M - SK_B; S_s[r] = S2; }

                // colp += exp2(z - u + 112)  (packed fma)
                const sk_u64 inv2 = pk2_(invSb, invSb);
                #pragma unroll
                for (int e = 0; e < 8; ++e)
                    colp2[e] = fma2_(z2[e], inv2, colp2[e]);
            }

            // stage per-warp column partials (conflict-free float4)
            {
                float4* sp = reinterpret_cast<float4*>(stg_p + wid * 512);
                #pragma unroll
                for (int k = 0; k < 4; ++k) {
                    float4 o4;
                    up2_(colp2[2*k],   o4.x, o4.y);
                    up2_(colp2[2*k+1], o4.z, o4.w);
                    sp[lane + 32 * k] = o4;
                }
            }
            __syncthreads();

            // combine: thread j (< 512) owns column j over 20 warp partials
            float dv = 0.0f;
            float Pl = 0.0f;
            if (tid < SK_N) {
                #pragma unroll
                for (int w = 0; w < 20; ++w) Pl += stg_p[w * 512 + tid];
                st_peer_f32(smem_b + (OFF_PEX + par * 512 + tid) * 4, peer, Pl);
            }
            cluster_sync_();   // release our DSMEM store / acquire peer's
            if (tid < SK_N) {
                const float P = Pl + pex[par * 512 + tid];   // > 0 by floor
                dv = lg2f_(P) - SK_B;
                v_s[tid] -= dv;          // nv convention: nv -= dv
            }
            const int active = __syncthreads_count(fabsf(dv) > SK_CONV);
            if (active == 0) break;   // identical in both CTAs -> coherent exit
        }

        // output: exp2(s + nv - u), u = Mb + log2(S2); packed, streaming
        {
            sk_u64 colv2[8];
            const float4* vr = reinterpret_cast<const float4*>(v_s);
            #pragma unroll
            for (int k = 0; k < 4; ++k) {
                float4 nv = vr[lane + 32 * k];
                colv2[2*k]   = pk2_(nv.x, nv.y);
                colv2[2*k+1] = pk2_(nv.z, nv.w);
            }
            #pragma unroll 1
            for (int rr = 0; rr < nrows; ++rr) {
                const int r = row0 + rwoff + rr;
                const float ur = M_s[r] + lg2f_(S_s[r]);   // true u (bias cancels)
                const sk_u64 mu2 = pk2_(-ur, -ur);
                const float4* xr = reinterpret_cast<const float4*>(X + (size_t)r * SK_N);
                float4* orow = reinterpret_cast<float4*>(O + (size_t)r * SK_N);
                #pragma unroll
                for (int k = 0; k < 4; ++k) {
                    float4 xv = __ldcs(xr + lane + 32 * k);
                    sk_u64 a2 = add2_(fma2_(pk2_(xv.x, xv.y), K2_2, colv2[2*k]),   mu2);
                    sk_u64 b2 = add2_(fma2_(pk2_(xv.z, xv.w), K2_2, colv2[2*k+1]), mu2);
                    float4 o;
                    { float a, b; up2_(a2, a, b); o.x = ex2f_(a); o.y = ex2f_(b); }
                    { float a, b; up2_(b2, a, b); o.z = ex2f_(a); o.w = ex2f_(b); }
                    __stcs(orow + lane + 32 * k, o);
                }
            }
        }
        // protect exchange buffers + v_s before the next matrix starts
        cluster_sync_();
        __syncthreads();
    }
}

extern "C" void kernel_launch(void* const* d_in, const int* in_sizes, int n_in,
                              void* d_out, int out_size)
{
    const float* x = (const float*)d_in[0];
    float* out = (float*)d_out;
    const int nmat = in_sizes[0] / (SK_N * SK_N);

    cudaFuncSetAttribute(sinkhorn_fused,
                         cudaFuncAttributeMaxDynamicSharedMemorySize, SK_SMEM_BYTES);

    int nclust = nmat < SK_NCLUST ? nmat : SK_NCLUST;
    sinkhorn_fused<<<2 * nclust, SK_THR, SK_SMEM_BYTES>>>(x, out, nmat);
}